// round 16
// baseline (speedup 1.0000x reference)
#include <cuda_runtime.h>
#include <cuda_fp16.h>
#include <stdint.h>
#include <math.h>

// Problem constants
#define BATCH   2
#define SEQ     2048
#define DIMM    2048
#define HEADS   16
#define DHEAD   128
#define INNER   2048
#define TOKENS  (BATCH*SEQ)
#define HIST    512
#define QSCALE  0.08838834764831845f

// Dense GEMM tiling (128x256, 512 threads, 1 CTA/SM)
#define BM 128
#define BN 256
#define BK 32
#define NT2 512

// Flash kernel smem: 5 tiles of 128 rows x 272B (QH, QL, KH, KL, V)
#define FROWB  272
#define FT_SZ  (128 * FROWB)
#define OFF_QH 0
#define OFF_QL (1 * FT_SZ)
#define OFF_KH (2 * FT_SZ)
#define OFF_KL (3 * FT_SZ)
#define OFF_V  (4 * FT_SZ)
#define FSMEM  (5 * FT_SZ)            // 174080

// fp32 scratch
__device__ float g_q[(size_t)TOKENS * INNER];
__device__ float g_k[(size_t)TOKENS * INNER];
// fp16 scratch
__device__ __half g_ah[(size_t)TOKENS * INNER];   // hs split hi; later attn-out (single)
__device__ __half g_al[(size_t)TOKENS * INNER];   // hs split lo
__device__ __half g_wqh[(size_t)INNER * DIMM];    // Q/K weights hi/lo split
__device__ __half g_wql[(size_t)INNER * DIMM];
__device__ __half g_wkh[(size_t)INNER * DIMM];
__device__ __half g_wkl[(size_t)INNER * DIMM];
__device__ __half g_wv[(size_t)INNER * DIMM];     // Wv full fp16 (2-term stage)
__device__ __half g_wo[(size_t)INNER * DIMM];     // Wo full fp16 (1-term stage)
__device__ __half g_qh[(size_t)TOKENS * INNER];
__device__ __half g_ql[(size_t)TOKENS * INNER];
__device__ __half g_kh[(size_t)TOKENS * INNER];
__device__ __half g_kl[(size_t)TOKENS * INNER];
__device__ __half g_vf[(size_t)TOKENS * INNER];   // V single fp16

__device__ __forceinline__ uint32_t smem_u32(const void* p) {
    uint32_t a;
    asm("{ .reg .u64 t; cvta.to.shared.u64 t, %1; cvt.u32.u64 %0, t; }" : "=r"(a) : "l"(p));
    return a;
}

#define CP16(dst, src) \
    asm volatile("cp.async.cg.shared.global [%0], [%1], 16;" \
        :: "r"(dst), "l"(__cvta_generic_to_global(src)) : "memory")
#define CP_COMMIT() asm volatile("cp.async.commit_group;" ::: "memory")
#define CP_WAIT(n)  asm volatile("cp.async.wait_group %0;" :: "n"(n) : "memory")

#define LDSM4(r, a) \
    asm volatile("ldmatrix.sync.aligned.m8n8.x4.shared.b16 {%0,%1,%2,%3}, [%4];" \
        : "=r"((r)[0]), "=r"((r)[1]), "=r"((r)[2]), "=r"((r)[3]) : "r"(a))
#define LDSM4T(r, a) \
    asm volatile("ldmatrix.sync.aligned.m8n8.x4.trans.shared.b16 {%0,%1,%2,%3}, [%4];" \
        : "=r"((r)[0]), "=r"((r)[1]), "=r"((r)[2]), "=r"((r)[3]) : "r"(a))

#define MMA16816(d, a, b0, b1) \
    asm volatile("mma.sync.aligned.m16n8k16.row.col.f32.f16.f16.f32 " \
        "{%0,%1,%2,%3}, {%4,%5,%6,%7}, {%8,%9}, {%0,%1,%2,%3};" \
        : "+f"((d)[0]), "+f"((d)[1]), "+f"((d)[2]), "+f"((d)[3]) \
        : "r"((a)[0]), "r"((a)[1]), "r"((a)[2]), "r"((a)[3]), "r"(b0), "r"(b1))

__device__ __forceinline__ uint32_t packh(float a, float b) {
    __half2 t = __floats2half2_rn(a, b);
    return *reinterpret_cast<uint32_t*>(&t);
}
__device__ __forceinline__ float hhf(float x) {
    return __half2float(__float2half_rn(x));
}

// ---------------------------------------------------------------------------
// fp32 -> fp16 hi/lo split; y selects hs / Wq / Wk.
// ---------------------------------------------------------------------------
__global__ void __launch_bounds__(256)
convert_split3(const float* __restrict__ x0, __half* __restrict__ h0,
               __half* __restrict__ l0, int n0,
               const float* __restrict__ x1, __half* __restrict__ h1,
               __half* __restrict__ l1, int n1,
               const float* __restrict__ x2, __half* __restrict__ h2,
               __half* __restrict__ l2, int n2)
{
    const float* x; __half *h, *l; int n;
    if (blockIdx.y == 0)      { x = x0; h = h0; l = l0; n = n0; }
    else if (blockIdx.y == 1) { x = x1; h = h1; l = l1; n = n1; }
    else                      { x = x2; h = h2; l = l2; n = n2; }
    if ((int)blockIdx.x >= n) return;
    int i = (blockIdx.x * 256 + threadIdx.x) * 4;
    float4 v = *reinterpret_cast<const float4*>(x + i);
    float a0 = hhf(v.x), a1 = hhf(v.y), a2 = hhf(v.z), a3 = hhf(v.w);
    *reinterpret_cast<uint2*>(h + i) = make_uint2(packh(a0, a1), packh(a2, a3));
    *reinterpret_cast<uint2*>(l + i) =
        make_uint2(packh(v.x - a0, v.y - a1), packh(v.z - a2, v.w - a3));
}

// fp32 -> single fp16; y-dim selects one of two tensors.
__global__ void __launch_bounds__(256)
convert_full2(const float* __restrict__ x0, __half* __restrict__ h0,
              const float* __restrict__ x1, __half* __restrict__ h1)
{
    const float* x = blockIdx.y ? x1 : x0;
    __half* h = blockIdx.y ? h1 : h0;
    int i = (blockIdx.x * 256 + threadIdx.x) * 4;
    float4 v = *reinterpret_cast<const float4*>(x + i);
    *reinterpret_cast<uint2*>(h + i) =
        make_uint2(packh(v.x, v.y), packh(v.z, v.w));
}

// ---------------------------------------------------------------------------
// Dense GEMM tile fill, 512 threads, 128x256 tile.
// Smem: AH @0 (10240B), AL @10240 (TERMS>=2), B(H) @OFFB (20480B),
//       BL @OFFB+20480 (TERMS==3). Rows padded to 80B.
// ---------------------------------------------------------------------------
template<int TERMS>
__device__ __forceinline__ void fill_stage_bt(uint32_t st,
    const __half* __restrict__ Ah, const __half* __restrict__ Al,
    const __half* __restrict__ Bh, const __half* __restrict__ Bl,
    int row0, int col0, int k0, int lda, int ldb, int tid)
{
    constexpr uint32_t OFFB = (TERMS == 1) ? 10240u : 20480u;
    // A: 128 rows x 32k = 512 x 16B per piece; 512 threads -> 1 copy each
    {
        int r = tid >> 2;
        int kc = (tid & 3) * 8;
        CP16(st + r * 80 + kc * 2, &Ah[(long long)(row0 + r) * lda + k0 + kc]);
        if (TERMS >= 2)
            CP16(st + 10240 + r * 80 + kc * 2,
                 &Al[(long long)(row0 + r) * lda + k0 + kc]);
    }
    // B: 256 rows x 32k = 1024 x 16B per piece; 2 copies/thread/piece
    #pragma unroll
    for (int l = 0; l < ((TERMS == 3) ? 4 : 2); l++) {
        int c = (tid + l * 512) & 1023;
        int r = c >> 2;
        int kc = (c & 3) * 8;
        const __half* src = (l < 2) ? Bh : Bl;
        uint32_t dst = st + OFFB + ((l < 2) ? 0u : 20480u) + r * 80 + kc * 2;
        CP16(dst, &src[(long long)(col0 + r) * ldb + k0 + kc]);
    }
}

// ---------------------------------------------------------------------------
// Dense GEMM core, 16 warps (4M x 4N), warp tile 32x64.
// ---------------------------------------------------------------------------
template<int TERMS, int OUTM>
__device__ __forceinline__ void gemm_body(
    const __half* __restrict__ Ah, const __half* __restrict__ Al,
    const __half* __restrict__ Bh, const __half* __restrict__ Bl,
    const float* __restrict__ bias,
    float* __restrict__ C, __half* __restrict__ Ch,
    int K, int lda, int ldb, int ldc, int row0, int col0, char* dynsm)
{
    constexpr uint32_t STAGE = (TERMS == 3) ? 61440u : (TERMS == 2) ? 40960u : 30720u;
    constexpr uint32_t OFFB  = (TERMS == 1) ? 10240u : 20480u;
    const int tid  = threadIdx.x;
    const int wid  = tid >> 5;
    const int lane = tid & 31;
    const int wm   = (wid & 3) * 32;
    const int wn   = (wid >> 2) * 64;
    const uint32_t smBase = smem_u32(dynsm);

    float acc[2][8][4];
    #pragma unroll
    for (int i = 0; i < 2; i++)
        #pragma unroll
        for (int j = 0; j < 8; j++)
            #pragma unroll
            for (int t = 0; t < 4; t++) acc[i][j][t] = 0.f;

    const int aRow = wm + (lane & 15);
    const int aColOff = (lane >> 4) << 3;
    const int bRow = wn + (lane & 7) + ((lane >> 4) << 3);
    const int bCol = ((lane >> 3) & 1) << 3;

    const int nch = K / BK;
    fill_stage_bt<TERMS>(smBase, Ah, Al, Bh, Bl, row0, col0, 0, lda, ldb, tid);
    CP_COMMIT();

    for (int ch = 0; ch < nch; ch++) {
        const uint32_t st = smBase + (ch & 1) * STAGE;
        if (ch + 1 < nch) {
            fill_stage_bt<TERMS>(smBase + ((ch + 1) & 1) * STAGE,
                                 Ah, Al, Bh, Bl, row0, col0, (ch + 1) * BK, lda, ldb, tid);
            CP_COMMIT();
            CP_WAIT(1);
        } else {
            CP_WAIT(0);
        }
        __syncthreads();

        #pragma unroll
        for (int kk = 0; kk < BK; kk += 16) {
            uint32_t ah[2][4], al[2][4];
            #pragma unroll
            for (int mi = 0; mi < 2; mi++) {
                uint32_t off = (aRow + mi * 16) * 80 + (kk + aColOff) * 2;
                LDSM4(ah[mi], st + off);
                if (TERMS >= 2) LDSM4(al[mi], st + 10240 + off);
            }
            #pragma unroll
            for (int ng = 0; ng < 4; ng++) {
                uint32_t bh[4], bl[4];
                uint32_t off = (bRow + ng * 16) * 80 + (kk + bCol) * 2;
                LDSM4(bh, st + OFFB + off);
                if (TERMS == 3) LDSM4(bl, st + OFFB + 20480 + off);
                #pragma unroll
                for (int mi = 0; mi < 2; mi++) {
                    #pragma unroll
                    for (int s = 0; s < 2; s++) {
                        float* d = acc[mi][ng * 2 + s];
                        MMA16816(d, ah[mi], bh[s * 2], bh[s * 2 + 1]);
                        if (TERMS == 3)
                            MMA16816(d, ah[mi], bl[s * 2], bl[s * 2 + 1]);
                        if (TERMS >= 2)
                            MMA16816(d, al[mi], bh[s * 2], bh[s * 2 + 1]);
                    }
                }
            }
        }
        __syncthreads();
    }

    #pragma unroll
    for (int mi = 0; mi < 2; mi++) {
        int r = row0 + wm + mi * 16 + (lane >> 2);
        #pragma unroll
        for (int nf = 0; nf < 8; nf++) {
            int c = col0 + wn + nf * 8 + (lane & 3) * 2;
            float b0 = 0.f, b1 = 0.f;
            if (bias) { b0 = bias[c]; b1 = bias[c + 1]; }
            float v00 = acc[mi][nf][0] + b0, v01 = acc[mi][nf][1] + b1;
            float v10 = acc[mi][nf][2] + b0, v11 = acc[mi][nf][3] + b1;
            long long i0 = (long long)r * ldc + c;
            long long i1 = (long long)(r + 8) * ldc + c;
            if (OUTM == 0) {
                *reinterpret_cast<float2*>(C + i0) = make_float2(v00, v01);
                *reinterpret_cast<float2*>(C + i1) = make_float2(v10, v11);
            } else {
                *reinterpret_cast<uint32_t*>(Ch + i0) = packh(v00, v01);
                *reinterpret_cast<uint32_t*>(Ch + i1) = packh(v10, v11);
            }
        }
    }
}

// ---------------------------------------------------------------------------
// Fused QKV projection: flat 1D grid of 768 tiles (128x256 each).
//   t in [0,256)   : Q projection (3-term, fp32 out)
//   t in [256,512) : K projection (3-term, fp32 out)
//   t in [512,768) : V projection (2-term, fp16 out) — short tiles fill tail
// ---------------------------------------------------------------------------
__global__ void __launch_bounds__(NT2, 1)
mma_gemm_qkv(const __half* __restrict__ Ah, const __half* __restrict__ Al,
             const __half* __restrict__ wqh, const __half* __restrict__ wql,
             const float* __restrict__ bq, float* __restrict__ q,
             const __half* __restrict__ wkh, const __half* __restrict__ wkl,
             const float* __restrict__ bk, float* __restrict__ k,
             const __half* __restrict__ wv, const float* __restrict__ bv,
             __half* __restrict__ vf)
{
    extern __shared__ __align__(16) char dynsm[];
    const int t = blockIdx.x;
    const int lt = t & 255;
    const int col0 = (lt & 7) * BN;
    const int row0 = (lt >> 3) * BM;
    if (t < 512) {
        const bool isK = (t >= 256);
        gemm_body<3, 0>(Ah, Al, isK ? wkh : wqh, isK ? wkl : wql,
                        isK ? bk : bq, isK ? k : q, nullptr,
                        DIMM, DIMM, DIMM, INNER, row0, col0, dynsm);
    } else {
        gemm_body<2, 2>(Ah, Al, wv, nullptr, bv, nullptr, vf,
                        DIMM, DIMM, DIMM, INNER, row0, col0, dynsm);
    }
}

// Single GEMM (out-projection, 1-term)
template<int TERMS, int OUTM>
__global__ void __launch_bounds__(NT2, 1)
mma_gemm(const __half* __restrict__ Ah, const __half* __restrict__ Al,
         const __half* __restrict__ Bh, const __half* __restrict__ Bl,
         const float* __restrict__ bias,
         float* __restrict__ C, __half* __restrict__ Ch,
         int K, int lda, int ldb, int ldc)
{
    extern __shared__ __align__(16) char dynsm[];
    gemm_body<TERMS, OUTM>(Ah, Al, Bh, Bl, bias, C, Ch, K, lda, ldb, ldc,
                           blockIdx.y * BM, blockIdx.x * BN, dynsm);
}

// ---------------------------------------------------------------------------
// Flash attention: S = Q@K^T (3-term fp16 split), online softmax,
// O = P@V (2-term: P hi/lo x V full fp16). O written single fp16.
// ---------------------------------------------------------------------------
__global__ void __launch_bounds__(256, 1)
flash_kernel(const __half* __restrict__ qh, const __half* __restrict__ ql,
             const __half* __restrict__ kh, const __half* __restrict__ kl,
             const __half* __restrict__ vf,
             __half* __restrict__ oh)
{
    extern __shared__ __align__(16) char fsm[];
    const uint32_t smb = smem_u32(fsm);
    const int tid  = threadIdx.x;
    const int wid  = tid >> 5;
    const int lane = tid & 31;
    const int q0   = blockIdx.x * 128;
    const int bh   = blockIdx.y;
    const long long tokb = (long long)(bh / HEADS) * SEQ;
    const int hcol = (bh % HEADS) * DHEAD;
    const int wm   = wid * 16;

    auto fill = [&](uint32_t off, const __half* __restrict__ src, int rowStart) {
        #pragma unroll
        for (int l = 0; l < 8; l++) {
            int idx = tid + l * 256;
            int r = idx >> 4, c = idx & 15;
            CP16(smb + off + r * FROWB + c * 16,
                 &src[(tokb + rowStart + r) * INNER + hcol + c * 8]);
        }
    };

    fill(OFF_QH, qh, q0); fill(OFF_QL, ql, q0);
    fill(OFF_KH, kh, 0);  fill(OFF_KL, kl, 0);
    CP_COMMIT();
    fill(OFF_V, vf, 0);
    CP_COMMIT();

    float oacc[16][4];
    #pragma unroll
    for (int g = 0; g < 16; g++)
        #pragma unroll
        for (int t = 0; t < 4; t++) oacc[g][t] = 0.f;
    float m0 = -1e30f, m1 = -1e30f, l0 = 0.f, l1 = 0.f;

    for (int it = 0; it < 16; it++) {
        CP_WAIT(1);
        __syncthreads();

        // ---- S = Q @ K^T (3-term) ----
        float sn[16][4];
        #pragma unroll
        for (int j = 0; j < 16; j++)
            #pragma unroll
            for (int t = 0; t < 4; t++) sn[j][t] = 0.f;

        #pragma unroll
        for (int k8 = 0; k8 < 8; k8++) {
            const int kk = k8 * 16;
            uint32_t qfh[4], qfl[4];
            uint32_t qoff = (uint32_t)(wm + (lane & 15)) * FROWB
                          + (uint32_t)(kk + ((lane >> 4) << 3)) * 2;
            LDSM4(qfh, smb + OFF_QH + qoff);
            LDSM4(qfl, smb + OFF_QL + qoff);
            #pragma unroll
            for (int g = 0; g < 8; g++) {
                uint32_t kbh[4], kbl[4];
                uint32_t koff = (uint32_t)(g * 16 + (lane & 7) + ((lane >> 4) << 3)) * FROWB
                              + (uint32_t)(kk + (((lane >> 3) & 1) << 3)) * 2;
                LDSM4(kbh, smb + OFF_KH + koff);
                LDSM4(kbl, smb + OFF_KL + koff);
                #pragma unroll
                for (int s2 = 0; s2 < 2; s2++) {
                    float* d = sn[g * 2 + s2];
                    MMA16816(d, qfh, kbh[s2 * 2], kbh[s2 * 2 + 1]);
                    MMA16816(d, qfh, kbl[s2 * 2], kbl[s2 * 2 + 1]);
                    MMA16816(d, qfl, kbh[s2 * 2], kbh[s2 * 2 + 1]);
                }
            }
        }
        __syncthreads();
        if (it < 15) {
            fill(OFF_KH, kh, (it + 1) * 128);
            fill(OFF_KL, kl, (it + 1) * 128);
            CP_COMMIT();
        }

        // ---- online softmax ----
        float rm0 = -1e30f, rm1 = -1e30f;
        #pragma unroll
        for (int j = 0; j < 16; j++) {
            rm0 = fmaxf(rm0, fmaxf(sn[j][0], sn[j][1]));
            rm1 = fmaxf(rm1, fmaxf(sn[j][2], sn[j][3]));
        }
        rm0 = fmaxf(rm0, __shfl_xor_sync(0xFFFFFFFFu, rm0, 1));
        rm0 = fmaxf(rm0, __shfl_xor_sync(0xFFFFFFFFu, rm0, 2));
        rm1 = fmaxf(rm1, __shfl_xor_sync(0xFFFFFFFFu, rm1, 1));
        rm1 = fmaxf(rm1, __shfl_xor_sync(0xFFFFFFFFu, rm1, 2));
        const float mn0 = fmaxf(m0, rm0), mn1 = fmaxf(m1, rm1);
        const float sc0 = __expf(m0 - mn0), sc1 = __expf(m1 - mn1);
        float rs0 = 0.f, rs1 = 0.f;
        #pragma unroll
        for (int j = 0; j < 16; j++) {
            sn[j][0] = __expf(sn[j][0] - mn0);
            sn[j][1] = __expf(sn[j][1] - mn0);
            sn[j][2] = __expf(sn[j][2] - mn1);
            sn[j][3] = __expf(sn[j][3] - mn1);
            rs0 += sn[j][0] + sn[j][1];
            rs1 += sn[j][2] + sn[j][3];
        }
        rs0 += __shfl_xor_sync(0xFFFFFFFFu, rs0, 1);
        rs0 += __shfl_xor_sync(0xFFFFFFFFu, rs0, 2);
        rs1 += __shfl_xor_sync(0xFFFFFFFFu, rs1, 1);
        rs1 += __shfl_xor_sync(0xFFFFFFFFu, rs1, 2);
        l0 = l0 * sc0 + rs0;  l1 = l1 * sc1 + rs1;
        m0 = mn0;  m1 = mn1;
        #pragma unroll
        for (int g = 0; g < 16; g++) {
            oacc[g][0] *= sc0;  oacc[g][1] *= sc0;
            oacc[g][2] *= sc1;  oacc[g][3] *= sc1;
        }

        if (it < 15) CP_WAIT(1); else CP_WAIT(0);
        __syncthreads();

        // ---- O += P @ V (2-term) ----
        #pragma unroll
        for (int s = 0; s < 8; s++) {
            const float* f0 = sn[2 * s];
            const float* f1 = sn[2 * s + 1];
            uint32_t pah[4], pal[4];
            {
                float h00 = hhf(f0[0]), h01 = hhf(f0[1]), h02 = hhf(f0[2]), h03 = hhf(f0[3]);
                float h10 = hhf(f1[0]), h11 = hhf(f1[1]), h12 = hhf(f1[2]), h13 = hhf(f1[3]);
                pah[0] = packh(h00, h01);  pal[0] = packh(f0[0] - h00, f0[1] - h01);
                pah[1] = packh(h02, h03);  pal[1] = packh(f0[2] - h02, f0[3] - h03);
                pah[2] = packh(h10, h11);  pal[2] = packh(f1[0] - h10, f1[1] - h11);
                pah[3] = packh(h12, h13);  pal[3] = packh(f1[2] - h12, f1[3] - h13);
            }
            #pragma unroll
            for (int g = 0; g < 8; g++) {
                uint32_t vb[4];
                uint32_t voff = (uint32_t)(s * 16 + (lane & 7) + (((lane >> 3) & 1) << 3)) * FROWB
                              + (uint32_t)(g * 16 + ((lane >> 4) << 3)) * 2;
                LDSM4T(vb, smb + OFF_V + voff);
                #pragma unroll
                for (int s2 = 0; s2 < 2; s2++) {
                    float* d = oacc[g * 2 + s2];
                    MMA16816(d, pah, vb[s2 * 2], vb[s2 * 2 + 1]);
                    MMA16816(d, pal, vb[s2 * 2], vb[s2 * 2 + 1]);
                }
            }
        }
        __syncthreads();
        if (it < 15) {
            fill(OFF_V, vf, (it + 1) * 128);
            CP_COMMIT();
        }
    }

    // ---- normalize + write O as single fp16 ----
    const float inv0 = 1.f / l0, inv1 = 1.f / l1;
    const int r0 = q0 + wm + (lane >> 2);
    #pragma unroll
    for (int g = 0; g < 16; g++) {
        const int c = hcol + g * 8 + (lane & 3) * 2;
        long long i0 = (tokb + r0) * INNER + c;
        long long i1 = (tokb + r0 + 8) * INNER + c;
        *reinterpret_cast<uint32_t*>(oh + i0) =
            packh(oacc[g][0] * inv0, oacc[g][1] * inv0);
        *reinterpret_cast<uint32_t*>(oh + i1) =
            packh(oacc[g][2] * inv1, oacc[g][3] * inv1);
    }
}

// ---------------------------------------------------------------------------
// Fused RMSNorm + RoPE + scales; fp32 in, fp16 hi/lo out (q and k).
// ---------------------------------------------------------------------------
__global__ void __launch_bounds__(256)
normrope_kernel(const float* __restrict__ q, const float* __restrict__ k,
                const float* __restrict__ rope,
                const float* __restrict__ wq, const float* __restrict__ wk,
                const float* __restrict__ hks,
                __half* __restrict__ qh, __half* __restrict__ ql,
                __half* __restrict__ kh, __half* __restrict__ kl)
{
    const int tok = blockIdx.x;
    const int s   = tok & (SEQ - 1);
    const bool isK = (blockIdx.y == 1);
    const float* x = (isK ? k : q) + (long long)tok * INNER;
    __half* outh = (isK ? kh : qh) + (long long)tok * INNER;
    __half* outl = (isK ? kl : ql) + (long long)tok * INNER;
    const float* w = isK ? wk : wq;
    const int tid = threadIdx.x;

    float2 vals[4];
    float ss = 0.f;
    #pragma unroll
    for (int l = 0; l < 4; l++) {
        int p = tid + 256 * l;
        float2 vv = *reinterpret_cast<const float2*>(&x[2 * p]);
        ss += vv.x * vv.x + vv.y * vv.y;
        vals[l] = vv;
    }
    #pragma unroll
    for (int off = 16; off; off >>= 1) ss += __shfl_xor_sync(0xFFFFFFFFu, ss, off);
    __shared__ float sred[8];
    if ((tid & 31) == 0) sred[tid >> 5] = ss;
    __syncthreads();
    float tot = 0.f;
    #pragma unroll
    for (int i = 0; i < 8; i++) tot += sred[i];
    const float inv = rsqrtf(tot * (1.f / (float)INNER) + 1e-5f);

    #pragma unroll
    for (int l = 0; l < 4; l++) {
        int p = tid + 256 * l;
        int h = p >> 6;
        int i = p & 63;
        float c  = rope[(long long)s * 256 + 2 * i];
        float sn = rope[(long long)s * 256 + 128 + 2 * i + 1];
        float x1 = vals[l].x * inv * w[2 * p];
        float x2 = vals[l].y * inv * w[2 * p + 1];
        float e = x1 * c - x2 * sn;
        float o = x1 * sn + x2 * c;
        float mult;
        if (isK) {
            mult = (s < HIST) ? (1.f + 9.f / (1.f + __expf(-hks[h]))) : 1.f;
        } else {
            mult = QSCALE;
        }
        e *= mult; o *= mult;
        float eh = hhf(e), oh2 = hhf(o);
        *reinterpret_cast<uint32_t*>(&outh[2 * p]) = packh(eh, oh2);
        *reinterpret_cast<uint32_t*>(&outl[2 * p]) = packh(e - eh, o - oh2);
    }
}

// ---------------------------------------------------------------------------
extern "C" void kernel_launch(void* const* d_in, const int* in_sizes, int n_in,
                              void* d_out, int out_size)
{
    const float* hs   = (const float*)d_in[0];
    const float* rope = (const float*)d_in[1];
    const float* Wq   = (const float*)d_in[2];
    const float* bq   = (const float*)d_in[3];
    const float* Wk   = (const float*)d_in[4];
    const float* bk   = (const float*)d_in[5];
    const float* Wv   = (const float*)d_in[6];
    const float* bv   = (const float*)d_in[7];
    const float* nqw  = (const float*)d_in[8];
    const float* nkw  = (const float*)d_in[9];
    const float* hks  = (const float*)d_in[10];
    const float* Wo   = (const float*)d_in[11];
    const float* bo   = (const float*)d_in[12];
    float* out = (float*)d_out;

    float *q, *k;
    __half *ah, *al, *wqh, *wql, *wkh, *wkl, *wv, *wo;
    __half *qh, *ql, *kh, *kl, *vf;
    cudaGetSymbolAddress((void**)&q,   g_q);
    cudaGetSymbolAddress((void**)&k,   g_k);
    cudaGetSymbolAddress((void**)&ah,  g_ah);
    cudaGetSymbolAddress((void**)&al,  g_al);
    cudaGetSymbolAddress((void**)&wqh, g_wqh);
    cudaGetSymbolAddress((void**)&wql, g_wql);
    cudaGetSymbolAddress((void**)&wkh, g_wkh);
    cudaGetSymbolAddress((void**)&wkl, g_wkl);
    cudaGetSymbolAddress((void**)&wv,  g_wv);
    cudaGetSymbolAddress((void**)&wo,  g_wo);
    cudaGetSymbolAddress((void**)&qh,  g_qh);
    cudaGetSymbolAddress((void**)&ql,  g_ql);
    cudaGetSymbolAddress((void**)&kh,  g_kh);
    cudaGetSymbolAddress((void**)&kl,  g_kl);
    cudaGetSymbolAddress((void**)&vf,  g_vf);

    cudaFuncSetAttribute(mma_gemm_qkv,
        cudaFuncAttributeMaxDynamicSharedMemorySize, 122880);
    cudaFuncSetAttribute(mma_gemm<1, 0>,
        cudaFuncAttributeMaxDynamicSharedMemorySize, 61440);
    cudaFuncSetAttribute(flash_kernel,
        cudaFuncAttributeMaxDynamicSharedMemorySize, FSMEM);

    // 0) converts: hs+Wq+Wk splits merged; Wv+Wo full merged
    const int nHS = TOKENS * DIMM / 1024;   // 8192 blocks
    const int nW  = INNER * DIMM / 1024;    // 4096 blocks
    convert_split3<<<dim3(nHS, 3), 256>>>(hs, ah, al, nHS,
                                          Wq, wqh, wql, nW,
                                          Wk, wkh, wkl, nW);
    convert_full2<<<dim3(nW, 2), 256>>>(Wv, wv, Wo, wo);

    // 1) QKV projections fused (128x256 tiles; V tiles fill the tail)
    mma_gemm_qkv<<<768, NT2, 122880>>>(ah, al,
        wqh, wql, bq, q,
        wkh, wkl, bk, k,
        wv, bv, vf);

    // 2) RMSNorm + RoPE + scales -> fp16 splits
    normrope_kernel<<<dim3(TOKENS, 2), 256>>>(q, k, rope, nqw, nkw, hks,
                                              qh, ql, kh, kl);

    // 3-5) Flash attention -> attn-out single fp16 into g_ah
    flash_kernel<<<dim3(SEQ / 128, BATCH * HEADS), 256, FSMEM>>>(
        qh, ql, kh, kl, vf, ah);

    // 6) Output projection (1-term, fp32 out + bias)
    dim3 g4(DIMM / BN, TOKENS / BM, 1);
    mma_gemm<1, 0><<<g4, NT2, 61440>>>(ah, nullptr, wo, nullptr, bo, out, nullptr,
        INNER, INNER, INNER, DIMM);
}